// round 1
// baseline (speedup 1.0000x reference)
#include <cuda_runtime.h>
#include <cuda_bf16.h>
#include <math.h>

// ---------------- constants ----------------
#define B_  64
#define S_  50
#define T_  50
#define R_  2
#define H_  256
#define G3_ 768
#define NU_ (B_*S_)          // 3200
#define NR_ (B_*R_)          // 128
#define MU_ (T_*NU_)         // 160000 utterance (t,n) rows
#define MR_ (T_*NR_)         // 6400
#define MC_ (S_*B_)          // 3200
#define TAB_N (B_*(S_+1)*H_) // 835584 uniform draws

// output offsets (f32 elements)
#define OFF_CTXOUT   0
#define OFF_CTXHID   819200
#define OFF_RESPOUT  835584
#define OFF_RESPHID  2473984
#define OFF_SPKEMB   2506752
#define OFF_MASK     3342336

// ---------------- scratch (static device memory; no allocation) ----------------
__device__ float g_tables[TAB_N];
__device__ float g_GIu[(size_t)MU_*G3_];   // ~491 MB
__device__ float g_GIc[(size_t)MC_*G3_];
__device__ float g_GIs[(size_t)MC_*G3_];
__device__ float g_GIr[(size_t)MR_*G3_];
__device__ float g_hu[NU_*H_];
__device__ float g_hc[B_*H_];
__device__ float g_hr[NR_*H_];
__device__ float g_hspk[B_*(S_+1)*H_];
__device__ float g_ctxin[MC_*2*H_];
__device__ float g_WTu_i[H_*G3_],  g_WTu_h[H_*G3_];
__device__ float g_WTc_i[2*H_*G3_],g_WTc_h[H_*G3_];
__device__ float g_WTr_i[H_*G3_],  g_WTr_h[H_*G3_];
__device__ float g_WTs_i[H_*G3_],  g_WTs_h[H_*G3_];
__device__ int   g_toku[MU_];
__device__ int   g_tokr[MR_];
__device__ int   g_present[B_*(S_+1)];

// ---------------- MT19937 (NumPy-exact) ----------------
__device__ __forceinline__ unsigned mt_twist_fn(unsigned u, unsigned v) {
    unsigned y = (u & 0x80000000u) | (v & 0x7fffffffu);
    return (y >> 1) ^ ((v & 1u) ? 0x9908b0dfu : 0u);
}
__device__ __forceinline__ unsigned mt_temper(unsigned y) {
    y ^= y >> 11;
    y ^= (y << 7)  & 0x9d2c5680u;
    y ^= (y << 15) & 0xefc60000u;
    y ^= y >> 18;
    return y;
}

// one block, 640 threads; 3-wave parallel twist (dep chain new[i] <- new[i-227])
__global__ void gen_tables_kernel(float* __restrict__ tables) {
    __shared__ unsigned bufA[624], bufB[624];
    const int tid = threadIdx.x;
    if (tid == 0) {
        unsigned s = 1u;
        bufA[0] = s;
        for (int i = 1; i < 624; i++) { s = 1812433253u * (s ^ (s >> 30)) + (unsigned)i; bufA[i] = s; }
    }
    __syncthreads();
    unsigned* cur = bufA;
    unsigned* nxt = bufB;
    const int NTW = (2*TAB_N + 623) / 624;   // 2679
    for (int tw = 0; tw < NTW; tw++) {
        if (tid < 227)
            nxt[tid] = cur[tid + 397] ^ mt_twist_fn(cur[tid], cur[tid + 1]);
        __syncthreads();
        if (tid >= 227 && tid < 454)
            nxt[tid] = nxt[tid - 227] ^ mt_twist_fn(cur[tid], cur[tid + 1]);
        __syncthreads();
        if (tid >= 454 && tid < 624) {
            unsigned v = (tid == 623) ? nxt[0] : cur[tid + 1];
            nxt[tid] = nxt[tid - 227] ^ mt_twist_fn(cur[tid], v);
        }
        __syncthreads();
        if (tid < 624 && (tid & 1) == 0) {
            int outIdx = tw * 312 + (tid >> 1);
            if (outIdx < TAB_N) {
                unsigned a = mt_temper(nxt[tid])     >> 5;   // 27 bits
                unsigned b = mt_temper(nxt[tid + 1]) >> 6;   // 26 bits
                double d = ((double)a * 67108864.0 + (double)b) * (1.0 / 9007199254740992.0);
                tables[outIdx] = (float)d;
            }
        }
        unsigned* t2 = cur; cur = nxt; nxt = t2;
        // 3 barriers/iter are sufficient: 'cur' is never written within an iter,
        // and next wave1 writes only the retired buffer.
    }
}

// ---------------- small utility kernels ----------------
__global__ void zero_f(float* p, int n) { int i = blockIdx.x * blockDim.x + threadIdx.x; if (i < n) p[i] = 0.f; }
__global__ void zero_i(int* p, int n)   { int i = blockIdx.x * blockDim.x + threadIdx.x; if (i < n) p[i] = 0; }
__global__ void copy_f(const float* s, float* d, int n) { int i = blockIdx.x * blockDim.x + threadIdx.x; if (i < n) d[i] = s[i]; }

// W [768, K] row-major -> WT [K, 768]
__global__ void transpose_w(const float* __restrict__ W, float* __restrict__ WT, int K) {
    int i = blockIdx.x * blockDim.x + threadIdx.x;
    if (i < 768 * K) { int g = i / K, k = i % K; WT[(size_t)k * 768 + g] = W[i]; }
}

__global__ void tok_utter_kernel(const int* __restrict__ ctx, int* __restrict__ toks) {
    int m = blockIdx.x * blockDim.x + threadIdx.x;
    if (m < MU_) { int t = m / NU_, n = m % NU_; toks[m] = ctx[n * T_ + t]; }
}
__global__ void tok_resp_kernel(const int* __restrict__ resp, int* __restrict__ toks) {
    int m = blockIdx.x * blockDim.x + threadIdx.x;
    if (m < MR_) { int t = m / NR_, n = m % NR_; toks[m] = resp[n * T_ + t]; }
}

__global__ void ctx_in_kernel(const float* __restrict__ hu, const float* __restrict__ tab,
                              const int* __restrict__ spk, float* __restrict__ cin) {
    int i = blockIdx.x * blockDim.x + threadIdx.x;
    if (i < MC_ * 2 * H_) {
        int row = i / (2 * H_), j = i % (2 * H_);
        int s = row / B_, b = row % B_;
        float v;
        if (j < H_) v = hu[((size_t)b * S_ + s) * H_ + j];
        else        v = tab[((size_t)b * (S_ + 1) + spk[b * S_ + s]) * H_ + (j - H_)];
        cin[i] = v;
    }
}

// ---------------- SGEMM with optional row gather: C[m,g] = sum_k A[m,k]*BT[k,g] + bias[g] ----------------
// BM=128, BN=64, BK=16, 256 threads, 8x4 per thread
__global__ __launch_bounds__(256) void gemm_bias_kernel(
    const float* __restrict__ A, const int* __restrict__ toks, const float* __restrict__ emb,
    const float* __restrict__ BT, const float* __restrict__ bias, float* __restrict__ C,
    int M, int K, int NT)
{
    __shared__ float As[16][128];
    __shared__ float Bs[16][64];
    const int tid = threadIdx.x;
    const int m0 = blockIdx.x * 128;
    const int n0 = blockIdx.y * 64;
    const int tr = tid / 16;          // 0..15 -> 8 rows
    const int tc = tid % 16;          // 0..15 -> 4 cols
    const int aRow0 = tid / 4;        // 0..63
    const int aK    = (tid % 4) * 4;  // 0,4,8,12
    const int bK    = tid / 16;       // 0..15
    const int bN    = (tid % 16) * 4;
    float acc[8][4];
    #pragma unroll
    for (int i = 0; i < 8; i++)
        #pragma unroll
        for (int j = 0; j < 4; j++) acc[i][j] = 0.f;

    for (int k0 = 0; k0 < K; k0 += 16) {
        #pragma unroll
        for (int i = 0; i < 2; i++) {
            int row = aRow0 + i * 64;
            int gm = m0 + row;
            const float* arow = toks ? (emb + (size_t)toks[gm] * K) : (A + (size_t)gm * K);
            float4 v = *(const float4*)(arow + k0 + aK);
            As[aK + 0][row] = v.x; As[aK + 1][row] = v.y;
            As[aK + 2][row] = v.z; As[aK + 3][row] = v.w;
        }
        float4 bv = *(const float4*)(BT + (size_t)(k0 + bK) * NT + n0 + bN);
        *(float4*)&Bs[bK][bN] = bv;
        __syncthreads();
        #pragma unroll
        for (int kk = 0; kk < 16; kk++) {
            float4 a0 = *(const float4*)&As[kk][tr * 8];
            float4 a1 = *(const float4*)&As[kk][tr * 8 + 4];
            float4 b4 = *(const float4*)&Bs[kk][tc * 4];
            float ar[8] = {a0.x, a0.y, a0.z, a0.w, a1.x, a1.y, a1.z, a1.w};
            float br[4] = {b4.x, b4.y, b4.z, b4.w};
            #pragma unroll
            for (int i = 0; i < 8; i++)
                #pragma unroll
                for (int j = 0; j < 4; j++) acc[i][j] += ar[i] * br[j];
        }
        __syncthreads();
    }
    float4 bb = *(const float4*)(bias + n0 + tc * 4);
    #pragma unroll
    for (int i = 0; i < 8; i++) {
        int gm = m0 + tr * 8 + i;
        float4 o;
        o.x = acc[i][0] + bb.x; o.y = acc[i][1] + bb.y;
        o.z = acc[i][2] + bb.z; o.w = acc[i][3] + bb.w;
        *(float4*)(C + (size_t)gm * NT + n0 + tc * 4) = o;
    }
}

// ---------------- fused GRU step: gh = h@WhhT + bhh, gates, in-place h update ----------------
// Each block: 16 rows x all 768 gate cols. Thread j owns cols (j, j+256, j+512) -> gates local.
// out_mode: 0 none, 1 contiguous [N,H] at outp, 2 response scatter (r = n%2, b = n/2)
__global__ __launch_bounds__(256) void gru_step_kernel(
    const float* __restrict__ GI, float* __restrict__ h,
    const float* __restrict__ WhhT, const float* __restrict__ bhh,
    float* __restrict__ outp, int out_mode, int t)
{
    __shared__ float hs[256 * 16];   // [k][r]
    const int tid = threadIdx.x;
    const int row0 = blockIdx.x * 16;
    {
        int r = tid / 16;
        int k0 = (tid % 16) * 16;
        const float* hp = h + (size_t)(row0 + r) * H_ + k0;
        #pragma unroll
        for (int i = 0; i < 4; i++) {
            float4 v = *(const float4*)(hp + i * 4);
            hs[(k0 + i * 4 + 0) * 16 + r] = v.x;
            hs[(k0 + i * 4 + 1) * 16 + r] = v.y;
            hs[(k0 + i * 4 + 2) * 16 + r] = v.z;
            hs[(k0 + i * 4 + 3) * 16 + r] = v.w;
        }
    }
    __syncthreads();
    const int j = tid;
    float accR[16], accZ[16], accN[16];
    #pragma unroll
    for (int r = 0; r < 16; r++) { accR[r] = 0.f; accZ[r] = 0.f; accN[r] = 0.f; }
    const float* W = WhhT + j;
    #pragma unroll 2
    for (int k = 0; k < 256; k++) {
        float w0 = W[(size_t)k * 768];
        float w1 = W[(size_t)k * 768 + 256];
        float w2 = W[(size_t)k * 768 + 512];
        const float4* hp = (const float4*)&hs[k * 16];
        float4 q0 = hp[0], q1 = hp[1], q2 = hp[2], q3 = hp[3];
        float hv[16] = {q0.x, q0.y, q0.z, q0.w, q1.x, q1.y, q1.z, q1.w,
                        q2.x, q2.y, q2.z, q2.w, q3.x, q3.y, q3.z, q3.w};
        #pragma unroll
        for (int r = 0; r < 16; r++) {
            accR[r] += hv[r] * w0;
            accZ[r] += hv[r] * w1;
            accN[r] += hv[r] * w2;
        }
    }
    const float br = bhh[j], bz = bhh[j + 256], bn = bhh[j + 512];
    #pragma unroll
    for (int r = 0; r < 16; r++) {
        int grow = row0 + r;
        const float* gi = GI + (size_t)grow * 768;
        float ir = gi[j], iz = gi[j + 256], inn = gi[j + 512];
        float rg = 1.f / (1.f + expf(-(ir + accR[r] + br)));
        float z  = 1.f / (1.f + expf(-(iz + accZ[r] + bz)));
        float hn = accN[r] + bn;
        float nn = tanhf(inn + rg * hn);
        float hold = hs[j * 16 + r];
        float hnew = (1.f - z) * nn + z * hold;
        h[(size_t)grow * H_ + j] = hnew;
        if (out_mode == 1) {
            outp[(size_t)grow * H_ + j] = hnew;
        } else if (out_mode == 2) {
            int rr = grow % R_, b = grow / R_;
            outp[(((size_t)rr * T_ + t) * B_ + b) * H_ + j] = hnew;
        }
    }
}

// ---------------- speaker GRU step: only the active speaker row per (b,s) updates ----------------
__global__ __launch_bounds__(256) void spk_step_kernel(
    const float* __restrict__ GIs, float* __restrict__ hspk,
    const int* __restrict__ spk, const float* __restrict__ WhhT,
    const float* __restrict__ bhh, int s)
{
    __shared__ float hv[H_];
    const int b = blockIdx.x;
    const int j = threadIdx.x;
    const int id = spk[b * S_ + s];
    float* hrow = hspk + ((size_t)b * (S_ + 1) + id) * H_;
    hv[j] = hrow[j];
    __syncthreads();
    float aR = 0.f, aZ = 0.f, aN = 0.f;
    const float* W = WhhT + j;
    #pragma unroll 4
    for (int k = 0; k < 256; k++) {
        float x = hv[k];
        aR += x * W[(size_t)k * 768];
        aZ += x * W[(size_t)k * 768 + 256];
        aN += x * W[(size_t)k * 768 + 512];
    }
    const float* gi = GIs + ((size_t)s * B_ + b) * 768;
    float rg = 1.f / (1.f + expf(-(gi[j] + aR + bhh[j])));
    float z  = 1.f / (1.f + expf(-(gi[j + 256] + aZ + bhh[j + 256])));
    float hn = aN + bhh[j + 512];
    float nn = tanhf(gi[j + 512] + rg * hn);
    float hold = hv[j];
    float hnew = (1.f - z) * nn + z * hold;
    hrow[j] = hnew;
}

__global__ void present_kernel(const int* __restrict__ spk, int* __restrict__ pres) {
    int i = blockIdx.x * blockDim.x + threadIdx.x;
    if (i < B_ * S_) { int b = i / S_; pres[b * (S_ + 1) + spk[i]] = 1; }
}

__global__ void spk_out_kernel(const float* __restrict__ hspk, const int* __restrict__ pres,
                               float* __restrict__ emb_out, float* __restrict__ mask_out) {
    int i = blockIdx.x * blockDim.x + threadIdx.x;
    if (i < B_ * (S_ + 1) * H_) {
        int ba = i / H_;
        int p = pres[ba];
        emb_out[i] = p ? hspk[i] : 0.f;
        if ((i % H_) == 0) {
            int a = ba % (S_ + 1);
            mask_out[ba] = (p && a > 0) ? 1.f : 0.f;
        }
    }
}

__global__ void resp_hidden_kernel(const float* __restrict__ hr, float* __restrict__ dst) {
    int i = blockIdx.x * blockDim.x + threadIdx.x;
    if (i < NR_ * H_) {
        int n = i / H_, j = i % H_;
        int r = n % R_, b = n / R_;
        dst[((size_t)r * B_ + b) * H_ + j] = hr[i];
    }
}

// ---------------- launch ----------------
extern "C" void kernel_launch(void* const* d_in, const int* in_sizes, int n_in,
                              void* d_out, int out_size)
{
    const int*   context  = (const int*)d_in[0];
    const int*   response = (const int*)d_in[1];
    const int*   spk      = (const int*)d_in[2];
    const float* emb_u    = (const float*)d_in[3];
    const float* emb_r    = (const float*)d_in[4];
    const float* uWih = (const float*)d_in[5];
    const float* uWhh = (const float*)d_in[6];
    const float* ubih = (const float*)d_in[7];
    const float* ubhh = (const float*)d_in[8];
    const float* cWih = (const float*)d_in[9];
    const float* cWhh = (const float*)d_in[10];
    const float* cbih = (const float*)d_in[11];
    const float* cbhh = (const float*)d_in[12];
    const float* rWih = (const float*)d_in[13];
    const float* rWhh = (const float*)d_in[14];
    const float* rbih = (const float*)d_in[15];
    const float* rbhh = (const float*)d_in[16];
    const float* sWih = (const float*)d_in[17];
    const float* sWhh = (const float*)d_in[18];
    const float* sbih = (const float*)d_in[19];
    const float* sbhh = (const float*)d_in[20];
    float* out = (float*)d_out;

    void *p;
    float *tab, *GIu, *GIc, *GIs, *GIr, *hu, *hc, *hr, *hspk, *cin;
    float *WTu_i, *WTu_h, *WTc_i, *WTc_h, *WTr_i, *WTr_h, *WTs_i, *WTs_h;
    int *toku, *tokr, *pres;
    cudaGetSymbolAddress(&p, g_tables); tab  = (float*)p;
    cudaGetSymbolAddress(&p, g_GIu);    GIu  = (float*)p;
    cudaGetSymbolAddress(&p, g_GIc);    GIc  = (float*)p;
    cudaGetSymbolAddress(&p, g_GIs);    GIs  = (float*)p;
    cudaGetSymbolAddress(&p, g_GIr);    GIr  = (float*)p;
    cudaGetSymbolAddress(&p, g_hu);     hu   = (float*)p;
    cudaGetSymbolAddress(&p, g_hc);     hc   = (float*)p;
    cudaGetSymbolAddress(&p, g_hr);     hr   = (float*)p;
    cudaGetSymbolAddress(&p, g_hspk);   hspk = (float*)p;
    cudaGetSymbolAddress(&p, g_ctxin);  cin  = (float*)p;
    cudaGetSymbolAddress(&p, g_WTu_i);  WTu_i = (float*)p;
    cudaGetSymbolAddress(&p, g_WTu_h);  WTu_h = (float*)p;
    cudaGetSymbolAddress(&p, g_WTc_i);  WTc_i = (float*)p;
    cudaGetSymbolAddress(&p, g_WTc_h);  WTc_h = (float*)p;
    cudaGetSymbolAddress(&p, g_WTr_i);  WTr_i = (float*)p;
    cudaGetSymbolAddress(&p, g_WTr_h);  WTr_h = (float*)p;
    cudaGetSymbolAddress(&p, g_WTs_i);  WTs_i = (float*)p;
    cudaGetSymbolAddress(&p, g_WTs_h);  WTs_h = (float*)p;
    cudaGetSymbolAddress(&p, g_toku);   toku = (int*)p;
    cudaGetSymbolAddress(&p, g_tokr);   tokr = (int*)p;
    cudaGetSymbolAddress(&p, g_present); pres = (int*)p;

    // --- constants / prep ---
    gen_tables_kernel<<<1, 640>>>(tab);
    transpose_w<<<(768*256+255)/256, 256>>>(uWih, WTu_i, 256);
    transpose_w<<<(768*256+255)/256, 256>>>(uWhh, WTu_h, 256);
    transpose_w<<<(768*512+255)/256, 256>>>(cWih, WTc_i, 512);
    transpose_w<<<(768*256+255)/256, 256>>>(cWhh, WTc_h, 256);
    transpose_w<<<(768*256+255)/256, 256>>>(rWih, WTr_i, 256);
    transpose_w<<<(768*256+255)/256, 256>>>(rWhh, WTr_h, 256);
    transpose_w<<<(768*256+255)/256, 256>>>(sWih, WTs_i, 256);
    transpose_w<<<(768*256+255)/256, 256>>>(sWhh, WTs_h, 256);
    tok_utter_kernel<<<(MU_+255)/256, 256>>>(context, toku);
    tok_resp_kernel<<<(MR_+255)/256, 256>>>(response, tokr);
    zero_f<<<(NU_*H_+255)/256, 256>>>(hu, NU_*H_);
    zero_f<<<(B_*H_+255)/256, 256>>>(hc, B_*H_);
    zero_f<<<(NR_*H_+255)/256, 256>>>(hr, NR_*H_);
    zero_f<<<(B_*(S_+1)*H_+255)/256, 256>>>(hspk, B_*(S_+1)*H_);
    zero_i<<<(B_*(S_+1)+255)/256, 256>>>(pres, B_*(S_+1));

    // --- utterance encoder ---
    {
        dim3 g(MU_/128, 768/64);
        gemm_bias_kernel<<<g, 256>>>(nullptr, toku, emb_u, WTu_i, ubih, GIu, MU_, 256, 768);
    }
    for (int t = 0; t < T_; t++)
        gru_step_kernel<<<NU_/16, 256>>>(GIu + (size_t)t*NU_*768, hu, WTu_h, ubhh, nullptr, 0, t);

    // --- context GRU ---
    ctx_in_kernel<<<(MC_*2*H_+255)/256, 256>>>(hu, tab, spk, cin);
    {
        dim3 g(MC_/128, 768/64);
        gemm_bias_kernel<<<g, 256>>>(cin, nullptr, nullptr, WTc_i, cbih, GIc, MC_, 512, 768);
    }
    for (int s = 0; s < S_; s++)
        gru_step_kernel<<<B_/16, 256>>>(GIc + (size_t)s*B_*768, hc, WTc_h, cbhh,
                                        out + OFF_CTXOUT + (size_t)s*B_*H_, 1, s);
    copy_f<<<(B_*H_+255)/256, 256>>>(out + OFF_CTXOUT + (size_t)(S_-1)*B_*H_, out + OFF_CTXHID, B_*H_);

    // --- speaker GRU (sparse update) ---
    {
        dim3 g(MC_/128, 768/64);
        gemm_bias_kernel<<<g, 256>>>(out + OFF_CTXOUT, nullptr, nullptr, WTs_i, sbih, GIs, MC_, 256, 768);
    }
    for (int s = 0; s < S_; s++)
        spk_step_kernel<<<B_, 256>>>(GIs, hspk, spk, WTs_h, sbhh, s);
    present_kernel<<<(B_*S_+255)/256, 256>>>(spk, pres);
    spk_out_kernel<<<(B_*(S_+1)*H_+255)/256, 256>>>(hspk, pres, out + OFF_SPKEMB, out + OFF_MASK);

    // --- response encoder ---
    {
        dim3 g(MR_/128, 768/64);
        gemm_bias_kernel<<<g, 256>>>(nullptr, tokr, emb_r, WTr_i, rbih, GIr, MR_, 256, 768);
    }
    for (int t = 0; t < T_; t++)
        gru_step_kernel<<<NR_/16, 256>>>(GIr + (size_t)t*NR_*768, hr, WTr_h, rbhh,
                                         out + OFF_RESPOUT, 2, t);
    resp_hidden_kernel<<<(NR_*H_+255)/256, 256>>>(hr, out + OFF_RESPHID);
}

// round 2
// speedup vs baseline: 1.6772x; 1.6772x over previous
#include <cuda_runtime.h>
#include <math.h>

typedef unsigned long long u64;

// ---------------- constants ----------------
#define B_  64
#define S_  50
#define T_  50
#define R_  2
#define H_  256
#define NU_ (B_*S_)          // 3200
#define NR_ (B_*R_)          // 128
#define MU_ (T_*NU_)         // 160000
#define MR_ (T_*NR_)         // 6400
#define MC_ (S_*B_)          // 3200
#define TAB_N (B_*(S_+1)*H_) // 835584

// output offsets (f32 elements)
#define OFF_CTXOUT   0
#define OFF_CTXHID   819200
#define OFF_RESPOUT  835584
#define OFF_RESPHID  2473984
#define OFF_SPKEMB   2506752
#define OFF_MASK     3342336

// ---------------- static device scratch ----------------
__device__ float g_tables[TAB_N];
__device__ float g_GIu[(size_t)MU_*768];
__device__ float g_GIc[(size_t)MC_*768];
__device__ float g_GIr[(size_t)MR_*768];
__device__ float g_hu[NU_*H_];
__device__ float g_hc[B_*H_];
__device__ float g_hr[NR_*H_];
__device__ float g_hspk[B_*(S_+1)*H_];
__device__ float g_ctxin[MC_*2*H_];
__device__ float g_WTu_i[H_*768],  g_WTu_h[H_*768];
__device__ float g_WTc_i[2*H_*768],g_WTc_h[H_*768];
__device__ float g_WTr_i[H_*768],  g_WTr_h[H_*768];
__device__ float g_WTs_i[H_*768],  g_WTs_h[H_*768];
__device__ int   g_toku[MU_];
__device__ int   g_tokr[MR_];
__device__ int   g_present[B_*(S_+1)];

// ---------------- f32x2 helpers ----------------
__device__ __forceinline__ u64 pack2(float lo, float hi) {
    u64 r; asm("mov.b64 %0, {%1,%2};" : "=l"(r) : "f"(lo), "f"(hi)); return r;
}
__device__ __forceinline__ void unpack2(u64 a, float& lo, float& hi) {
    asm("mov.b64 {%0,%1}, %2;" : "=f"(lo), "=f"(hi) : "l"(a));
}
__device__ __forceinline__ u64 ffma2(u64 a, u64 b, u64 c) {
    u64 d; asm("fma.rn.f32x2 %0, %1, %2, %3;" : "=l"(d) : "l"(a), "l"(b), "l"(c)); return d;
}

// ---------------- MT19937 (NumPy-exact), 256-thread body ----------------
__device__ __forceinline__ unsigned mt_twist_fn(unsigned u, unsigned v) {
    unsigned y = (u & 0x80000000u) | (v & 0x7fffffffu);
    return (y >> 1) ^ ((v & 1u) ? 0x9908b0dfu : 0u);
}
__device__ __forceinline__ unsigned mt_temper(unsigned y) {
    y ^= y >> 11; y ^= (y << 7) & 0x9d2c5680u; y ^= (y << 15) & 0xefc60000u; y ^= y >> 18;
    return y;
}
__device__ void mt_body(float* __restrict__ tables, unsigned* bufA, unsigned* bufB) {
    const int tid = threadIdx.x;
    if (tid == 0) {
        unsigned s = 1u; bufA[0] = s;
        for (int i = 1; i < 624; i++) { s = 1812433253u * (s ^ (s >> 30)) + (unsigned)i; bufA[i] = s; }
    }
    __syncthreads();
    unsigned* cur = bufA; unsigned* nxt = bufB;
    const int NTW = (2*TAB_N + 623) / 624;   // 2679
    for (int tw = 0; tw < NTW; tw++) {
        if (tid < 227) nxt[tid] = cur[tid + 397] ^ mt_twist_fn(cur[tid], cur[tid + 1]);
        __syncthreads();
        if (tid < 227) { int i = 227 + tid; nxt[i] = nxt[i - 227] ^ mt_twist_fn(cur[i], cur[i + 1]); }
        __syncthreads();
        if (tid < 170) {
            int i = 454 + tid;
            unsigned v = (i == 623) ? nxt[0] : cur[i + 1];
            nxt[i] = nxt[i - 227] ^ mt_twist_fn(cur[i], v);
        }
        __syncthreads();
        for (int o = tid; o < 312; o += 256) {
            int outIdx = tw * 312 + o;
            if (outIdx < TAB_N) {
                unsigned a  = mt_temper(nxt[2*o])   >> 5;
                unsigned bv = mt_temper(nxt[2*o+1]) >> 6;
                tables[outIdx] = (float)(((double)a * 67108864.0 + (double)bv) * (1.0 / 9007199254740992.0));
            }
        }
        __syncthreads();
        unsigned* t2 = cur; cur = nxt; nxt = t2;
    }
}

// ---------------- GEMM body: C[m,g] = A[m,:]·BT[:,g] + bias[g]; BM=BN=128, BK=16, 8x8/thread, FFMA2 ----------------
__device__ __forceinline__ void gemm_body(
    const float* __restrict__ A, const int* __restrict__ toks, const float* __restrict__ emb,
    const float* __restrict__ BT, const float* __restrict__ bias, float* __restrict__ C,
    int m0, int n0, int K, float* As, float* Bs)
{
    const int tid  = threadIdx.x;
    const int arow = tid >> 2;
    const int akc  = (tid & 3) << 2;
    const int bk   = tid >> 4;
    const int bc   = (tid & 15) << 3;
    const int tr   = tid >> 4;
    const int tc   = tid & 15;

    const float* arp0;
    const float* arp1;
    {
        int gm0 = m0 + arow, gm1 = m0 + arow + 64;
        arp0 = toks ? (emb + (size_t)__ldg(toks + gm0) * K) : (A + (size_t)gm0 * K);
        arp1 = toks ? (emb + (size_t)__ldg(toks + gm1) * K) : (A + (size_t)gm1 * K);
    }
    float4 ra0 = *(const float4*)(arp0 + akc);
    float4 ra1 = *(const float4*)(arp1 + akc);
    float4 rb0 = *(const float4*)(BT + (size_t)bk * 768 + n0 + bc);
    float4 rb1 = *(const float4*)(BT + (size_t)bk * 768 + n0 + bc + 4);
    {
        As[(akc+0)*128 + arow] = ra0.x; As[(akc+1)*128 + arow] = ra0.y;
        As[(akc+2)*128 + arow] = ra0.z; As[(akc+3)*128 + arow] = ra0.w;
        As[(akc+0)*128 + arow+64] = ra1.x; As[(akc+1)*128 + arow+64] = ra1.y;
        As[(akc+2)*128 + arow+64] = ra1.z; As[(akc+3)*128 + arow+64] = ra1.w;
        *(float4*)(Bs + bk*128 + bc)     = rb0;
        *(float4*)(Bs + bk*128 + bc + 4) = rb1;
    }
    __syncthreads();

    u64 acc[8][4];
    #pragma unroll
    for (int i = 0; i < 8; i++)
        #pragma unroll
        for (int j = 0; j < 4; j++) acc[i][j] = 0ull;

    int buf = 0;
    for (int k0 = 16; k0 <= K; k0 += 16) {
        const bool more = (k0 < K);
        if (more) {
            ra0 = *(const float4*)(arp0 + k0 + akc);
            ra1 = *(const float4*)(arp1 + k0 + akc);
            rb0 = *(const float4*)(BT + (size_t)(k0 + bk) * 768 + n0 + bc);
            rb1 = *(const float4*)(BT + (size_t)(k0 + bk) * 768 + n0 + bc + 4);
        }
        const float* Asb = As + buf * 2048;
        const float* Bsb = Bs + buf * 2048;
        #pragma unroll
        for (int kk = 0; kk < 16; kk++) {
            float4 av0 = *(const float4*)(Asb + kk*128 + tr*8);
            float4 av1 = *(const float4*)(Asb + kk*128 + tr*8 + 4);
            u64 bb0 = *(const u64*)(Bsb + kk*128 + tc*4);
            u64 bb1 = *(const u64*)(Bsb + kk*128 + tc*4 + 2);
            u64 bb2 = *(const u64*)(Bsb + kk*128 + 64 + tc*4);
            u64 bb3 = *(const u64*)(Bsb + kk*128 + 64 + tc*4 + 2);
            float av[8] = {av0.x, av0.y, av0.z, av0.w, av1.x, av1.y, av1.z, av1.w};
            #pragma unroll
            for (int i = 0; i < 8; i++) {
                u64 aa = pack2(av[i], av[i]);
                acc[i][0] = ffma2(aa, bb0, acc[i][0]);
                acc[i][1] = ffma2(aa, bb1, acc[i][1]);
                acc[i][2] = ffma2(aa, bb2, acc[i][2]);
                acc[i][3] = ffma2(aa, bb3, acc[i][3]);
            }
        }
        if (more) {
            float* Asb1 = As + (buf ^ 1) * 2048;
            float* Bsb1 = Bs + (buf ^ 1) * 2048;
            Asb1[(akc+0)*128 + arow] = ra0.x; Asb1[(akc+1)*128 + arow] = ra0.y;
            Asb1[(akc+2)*128 + arow] = ra0.z; Asb1[(akc+3)*128 + arow] = ra0.w;
            Asb1[(akc+0)*128 + arow+64] = ra1.x; Asb1[(akc+1)*128 + arow+64] = ra1.y;
            Asb1[(akc+2)*128 + arow+64] = ra1.z; Asb1[(akc+3)*128 + arow+64] = ra1.w;
            *(float4*)(Bsb1 + bk*128 + bc)     = rb0;
            *(float4*)(Bsb1 + bk*128 + bc + 4) = rb1;
        }
        __syncthreads();
        buf ^= 1;
    }

    float4 bba = *(const float4*)(bias + n0 + tc*4);
    float4 bbb = *(const float4*)(bias + n0 + 64 + tc*4);
    #pragma unroll
    for (int i = 0; i < 8; i++) {
        int gm = m0 + tr*8 + i;
        float x0,x1,x2,x3,y0,y1,y2,y3;
        unpack2(acc[i][0], x0, x1); unpack2(acc[i][1], x2, x3);
        unpack2(acc[i][2], y0, y1); unpack2(acc[i][3], y2, y3);
        float4 o0 = make_float4(x0+bba.x, x1+bba.y, x2+bba.z, x3+bba.w);
        float4 o1 = make_float4(y0+bbb.x, y1+bbb.y, y2+bbb.z, y3+bbb.w);
        *(float4*)(C + (size_t)gm*768 + n0 + tc*4)      = o0;
        *(float4*)(C + (size_t)gm*768 + n0 + 64 + tc*4) = o1;
    }
}

// ---------------- mega GEMM: utter (7500 blocks) + resp (300) + MT19937 (1) ----------------
__global__ __launch_bounds__(256) void mega_gemm_kernel(
    const float* __restrict__ emb_u, const float* __restrict__ emb_r,
    const int* __restrict__ toku, const int* __restrict__ tokr,
    const float* __restrict__ WTu_i, const float* __restrict__ ubih,
    const float* __restrict__ WTr_i, const float* __restrict__ rbih,
    float* __restrict__ GIu, float* __restrict__ GIr, float* __restrict__ tables)
{
    __shared__ float As[2*16*128];
    __shared__ float Bs[2*16*128];
    __shared__ unsigned mtA[624], mtB[624];
    int b = blockIdx.x;
    if (b < 7500) {
        int mb = b % 1250, nb = b / 1250;
        gemm_body(nullptr, toku, emb_u, WTu_i, ubih, GIu, mb*128, nb*128, 256, As, Bs);
    } else if (b < 7800) {
        int b2 = b - 7500;
        int mb = b2 % 50, nb = b2 / 50;
        gemm_body(nullptr, tokr, emb_r, WTr_i, rbih, GIr, mb*128, nb*128, 256, As, Bs);
    } else {
        mt_body(tables, mtA, mtB);
    }
}

__global__ __launch_bounds__(256) void gemm_ctx_kernel(
    const float* __restrict__ cin, const float* __restrict__ WTc_i,
    const float* __restrict__ cbih, float* __restrict__ GIc)
{
    __shared__ float As[2*16*128];
    __shared__ float Bs[2*16*128];
    int mb = blockIdx.x % 25, nb = blockIdx.x / 25;
    gemm_body(cin, nullptr, nullptr, WTc_i, cbih, GIc, mb*128, nb*128, 512, As, Bs);
}

// ---------------- GRU step body (FFMA2, row-pair accumulators) ----------------
template<int ROWS>
__device__ __forceinline__ void gru_body(
    const float* __restrict__ GI, float* __restrict__ h,
    const float* __restrict__ WT, const float* __restrict__ bhh,
    float* __restrict__ outp, int out_mode, int t, int row0, float* hs)
{
    constexpr int PS = ROWS + 2;
    const int tid = threadIdx.x;
    for (int idx = tid; idx < ROWS*256; idx += 256) {
        int r = idx >> 8;
        int k = idx & 255;
        hs[k*PS + r] = h[(size_t)(row0 + r)*256 + k];
    }
    __syncthreads();
    u64 aR[ROWS/2], aZ[ROWS/2], aN[ROWS/2];
    #pragma unroll
    for (int p = 0; p < ROWS/2; p++) { aR[p]=0ull; aZ[p]=0ull; aN[p]=0ull; }
    const float* Wp = WT + tid;
    #pragma unroll 4
    for (int k = 0; k < 256; k++) {
        float w0 = __ldg(Wp + (size_t)k*768);
        float w1 = __ldg(Wp + (size_t)k*768 + 256);
        float w2 = __ldg(Wp + (size_t)k*768 + 512);
        u64 W0 = pack2(w0, w0), W1 = pack2(w1, w1), W2 = pack2(w2, w2);
        const u64* hp = (const u64*)(hs + k*PS);
        #pragma unroll
        for (int p = 0; p < ROWS/2; p++) {
            u64 hv = hp[p];
            aR[p] = ffma2(hv, W0, aR[p]);
            aZ[p] = ffma2(hv, W1, aZ[p]);
            aN[p] = ffma2(hv, W2, aN[p]);
        }
    }
    const float br = bhh[tid], bz = bhh[tid+256], bn = bhh[tid+512];
    #pragma unroll
    for (int p = 0; p < ROWS/2; p++) {
        float aRl,aRh,aZl,aZh,aNl,aNh;
        unpack2(aR[p], aRl, aRh); unpack2(aZ[p], aZl, aZh); unpack2(aN[p], aNl, aNh);
        #pragma unroll
        for (int q = 0; q < 2; q++) {
            int r = 2*p + q;
            float accR = q ? aRh : aRl;
            float accZ = q ? aZh : aZl;
            float accN = q ? aNh : aNl;
            int grow = row0 + r;
            const float* gi = GI + (size_t)grow*768;
            float ir = gi[tid], iz = gi[tid+256], inn = gi[tid+512];
            float rg = 1.f / (1.f + expf(-(ir + accR + br)));
            float z  = 1.f / (1.f + expf(-(iz + accZ + bz)));
            float nn = tanhf(inn + rg * (accN + bn));
            float hold = hs[tid*PS + r];
            float hnew = (1.f - z) * nn + z * hold;
            h[(size_t)grow*256 + tid] = hnew;
            if (out_mode == 1) {
                outp[(size_t)grow*256 + tid] = hnew;
            } else if (out_mode == 2) {
                int rr = grow & 1, bb = grow >> 1;
                outp[(((size_t)rr*T_ + t)*B_ + bb)*256 + tid] = hnew;
            }
        }
    }
}

// utter (100 blocks x 32 rows) + resp (16 blocks x 8 rows) in one launch per step
__global__ __launch_bounds__(256) void step_ur_kernel(
    const float* __restrict__ GIu, const float* __restrict__ GIr,
    float* __restrict__ hu, float* __restrict__ hr,
    const float* __restrict__ WTu_h, const float* __restrict__ ubhh,
    const float* __restrict__ WTr_h, const float* __restrict__ rbhh,
    float* __restrict__ respout, int t)
{
    __shared__ float hs[256*34];
    if (blockIdx.x < 100)
        gru_body<32>(GIu + (size_t)t*NU_*768, hu, WTu_h, ubhh, nullptr, 0, t, blockIdx.x*32, hs);
    else
        gru_body<8>(GIr + (size_t)t*NR_*768, hr, WTr_h, rbhh, respout, 2, t, (blockIdx.x - 100)*8, hs);
}

// ---------------- speaker step body: only active row per batch updates ----------------
__device__ void spk_body(const float* __restrict__ ctxout_s,
                         float* __restrict__ hspk, const int* __restrict__ spk,
                         const float* __restrict__ WTi, const float* __restrict__ WTh,
                         const float* __restrict__ bih, const float* __restrict__ bhh,
                         int s, int b0, float* sm)
{
    const int tid = threadIdx.x;
    float* cs  = sm;             // [k*6 + r]
    float* hsv = sm + 256*6;     // [k*6 + r]
    int id[4];
    #pragma unroll
    for (int r = 0; r < 4; r++) id[r] = spk[(b0 + r)*S_ + s];
    for (int idx = tid; idx < 4*256; idx += 256) {
        int r = idx >> 8, k = idx & 255;
        cs[k*6 + r]  = ctxout_s[(size_t)(b0 + r)*256 + k];
        hsv[k*6 + r] = hspk[((size_t)(b0 + r)*(S_+1) + id[r])*256 + k];
    }
    __syncthreads();
    u64 iR[2]={0ull,0ull}, iZ[2]={0ull,0ull}, iN[2]={0ull,0ull};
    u64 hR[2]={0ull,0ull}, hZ[2]={0ull,0ull}, hN[2]={0ull,0ull};
    #pragma unroll 2
    for (int k = 0; k < 256; k++) {
        float wi0 = __ldg(WTi + (size_t)k*768 + tid);
        float wi1 = __ldg(WTi + (size_t)k*768 + 256 + tid);
        float wi2 = __ldg(WTi + (size_t)k*768 + 512 + tid);
        float wh0 = __ldg(WTh + (size_t)k*768 + tid);
        float wh1 = __ldg(WTh + (size_t)k*768 + 256 + tid);
        float wh2 = __ldg(WTh + (size_t)k*768 + 512 + tid);
        u64 Wi0 = pack2(wi0,wi0), Wi1 = pack2(wi1,wi1), Wi2 = pack2(wi2,wi2);
        u64 Wh0 = pack2(wh0,wh0), Wh1 = pack2(wh1,wh1), Wh2 = pack2(wh2,wh2);
        const u64* cp = (const u64*)(cs + k*6);
        const u64* hp = (const u64*)(hsv + k*6);
        #pragma unroll
        for (int p = 0; p < 2; p++) {
            u64 cv = cp[p], hv = hp[p];
            iR[p] = ffma2(cv, Wi0, iR[p]); iZ[p] = ffma2(cv, Wi1, iZ[p]); iN[p] = ffma2(cv, Wi2, iN[p]);
            hR[p] = ffma2(hv, Wh0, hR[p]); hZ[p] = ffma2(hv, Wh1, hZ[p]); hN[p] = ffma2(hv, Wh2, hN[p]);
        }
    }
    const float bi0 = bih[tid], bi1 = bih[tid+256], bi2 = bih[tid+512];
    const float bh0 = bhh[tid], bh1 = bhh[tid+256], bh2 = bhh[tid+512];
    #pragma unroll
    for (int p = 0; p < 2; p++) {
        float iRl,iRh,iZl,iZh,iNl,iNh,hRl,hRh,hZl,hZh,hNl,hNh;
        unpack2(iR[p],iRl,iRh); unpack2(iZ[p],iZl,iZh); unpack2(iN[p],iNl,iNh);
        unpack2(hR[p],hRl,hRh); unpack2(hZ[p],hZl,hZh); unpack2(hN[p],hNl,hNh);
        #pragma unroll
        for (int q = 0; q < 2; q++) {
            int r = 2*p + q;
            float giR = (q ? iRh : iRl) + bi0;
            float giZ = (q ? iZh : iZl) + bi1;
            float giN = (q ? iNh : iNl) + bi2;
            float ghR = (q ? hRh : hRl) + bh0;
            float ghZ = (q ? hZh : hZl) + bh1;
            float ghN = (q ? hNh : hNl) + bh2;
            float rg = 1.f / (1.f + expf(-(giR + ghR)));
            float z  = 1.f / (1.f + expf(-(giZ + ghZ)));
            float nn = tanhf(giN + rg * ghN);
            float hold = hsv[tid*6 + r];
            float hnew = (1.f - z) * nn + z * hold;
            hspk[((size_t)(b0 + r)*(S_+1) + id[r])*256 + tid] = hnew;
        }
    }
}

// ctx step i (16 blocks x 4 rows) + spk step i-1 (16 blocks x 4 batches), pipelined
__global__ __launch_bounds__(256) void step_cs_kernel(
    const float* __restrict__ GIc, float* __restrict__ hc,
    const float* __restrict__ WTc_h, const float* __restrict__ cbhh,
    float* __restrict__ ctxout, float* __restrict__ hspk, const int* __restrict__ spk,
    const float* __restrict__ WTs_i, const float* __restrict__ WTs_h,
    const float* __restrict__ sbih, const float* __restrict__ sbhh, int i)
{
    __shared__ float sm[256*12];
    if (blockIdx.x < 16) {
        if (i < S_)
            gru_body<4>(GIc + (size_t)i*B_*768, hc, WTc_h, cbhh,
                        ctxout + (size_t)i*B_*256, 1, i, blockIdx.x*4, sm);
    } else {
        int s = i - 1;
        if (s >= 0)
            spk_body(ctxout + (size_t)s*B_*256, hspk, spk, WTs_i, WTs_h, sbih, sbhh,
                     s, (blockIdx.x - 16)*4, sm);
    }
}

// ---------------- prep kernel: transposes + token remap + zero + present ----------------
#define SEG_T256 196608
#define SEG_T512 393216
#define PREP_TOTAL (196608*7 + 393216 + 160000 + 6400 + 819200 + 16384 + 32768 + 835584 + 3264)

__global__ void prep_kernel(
    const int* __restrict__ context, const int* __restrict__ response, const int* __restrict__ spk,
    const float* __restrict__ uWih, const float* __restrict__ uWhh,
    const float* __restrict__ cWih, const float* __restrict__ cWhh,
    const float* __restrict__ rWih, const float* __restrict__ rWhh,
    const float* __restrict__ sWih, const float* __restrict__ sWhh,
    float* __restrict__ WTu_i, float* __restrict__ WTu_h,
    float* __restrict__ WTc_i, float* __restrict__ WTc_h,
    float* __restrict__ WTr_i, float* __restrict__ WTr_h,
    float* __restrict__ WTs_i, float* __restrict__ WTs_h,
    int* __restrict__ toku, int* __restrict__ tokr,
    float* __restrict__ hu, float* __restrict__ hc, float* __restrict__ hr,
    float* __restrict__ hspk, int* __restrict__ pres)
{
    long i = (long)blockIdx.x*256 + threadIdx.x;
    if (i >= PREP_TOTAL) return;
    if (i < SEG_T256) { int g = i >> 8, k = i & 255; WTu_i[k*768 + g] = uWih[i]; return; }
    i -= SEG_T256;
    if (i < SEG_T256) { int g = i >> 8, k = i & 255; WTu_h[k*768 + g] = uWhh[i]; return; }
    i -= SEG_T256;
    if (i < SEG_T512) { int g = (int)(i / 512), k = (int)(i % 512); WTc_i[k*768 + g] = cWih[i]; return; }
    i -= SEG_T512;
    if (i < SEG_T256) { int g = i >> 8, k = i & 255; WTc_h[k*768 + g] = cWhh[i]; return; }
    i -= SEG_T256;
    if (i < SEG_T256) { int g = i >> 8, k = i & 255; WTr_i[k*768 + g] = rWih[i]; return; }
    i -= SEG_T256;
    if (i < SEG_T256) { int g = i >> 8, k = i & 255; WTr_h[k*768 + g] = rWhh[i]; return; }
    i -= SEG_T256;
    if (i < SEG_T256) { int g = i >> 8, k = i & 255; WTs_i[k*768 + g] = sWih[i]; return; }
    i -= SEG_T256;
    if (i < SEG_T256) { int g = i >> 8, k = i & 255; WTs_h[k*768 + g] = sWhh[i]; return; }
    i -= SEG_T256;
    if (i < MU_) { int t = (int)(i / NU_), n = (int)(i % NU_); toku[i] = context[n*T_ + t]; return; }
    i -= MU_;
    if (i < MR_) { int t = (int)(i / NR_), n = (int)(i % NR_); tokr[i] = response[n*T_ + t]; return; }
    i -= MR_;
    if (i < NU_*H_) { hu[i] = 0.f; return; }
    i -= NU_*H_;
    if (i < B_*H_) { hc[i] = 0.f; return; }
    i -= B_*H_;
    if (i < NR_*H_) { hr[i] = 0.f; return; }
    i -= NR_*H_;
    if (i < B_*(S_+1)*H_) { hspk[i] = 0.f; return; }
    i -= B_*(S_+1)*H_;
    {
        int b = (int)(i / (S_+1)), a = (int)(i % (S_+1));
        int p = 0;
        for (int s = 0; s < S_; s++) p |= (spk[b*S_ + s] == a);
        pres[i] = p;
    }
}

// ---------------- ctx input gather ----------------
__global__ void ctx_in_kernel(const float* __restrict__ hu, const float* __restrict__ tab,
                              const int* __restrict__ spk, float* __restrict__ cin) {
    int i = blockIdx.x * blockDim.x + threadIdx.x;
    if (i < MC_ * 2 * H_) {
        int row = i / (2*H_), j = i % (2*H_);
        int s = row / B_, b = row % B_;
        float v;
        if (j < H_) v = hu[((size_t)b*S_ + s)*H_ + j];
        else        v = tab[((size_t)b*(S_+1) + spk[b*S_ + s])*H_ + (j - H_)];
        cin[i] = v;
    }
}

// ---------------- epilogue: ctxhid copy + resp_hidden scatter + spk outputs ----------------
#define EPI_TOTAL (16384 + 32768 + 835584)
__global__ void epilogue_kernel(float* __restrict__ out, const float* __restrict__ hr,
                                const float* __restrict__ hspk, const int* __restrict__ pres)
{
    long i = (long)blockIdx.x*256 + threadIdx.x;
    if (i >= EPI_TOTAL) return;
    if (i < 16384) { out[OFF_CTXHID + i] = out[OFF_CTXOUT + (size_t)(S_-1)*B_*H_ + i]; return; }
    i -= 16384;
    if (i < 32768) {
        int n = (int)(i >> 8), c = (int)(i & 255);
        int r = n % R_, b = n / R_;
        out[OFF_RESPHID + ((size_t)r*B_ + b)*H_ + c] = hr[i];
        return;
    }
    i -= 32768;
    {
        int ba = (int)(i >> 8);
        int p = pres[ba];
        out[OFF_SPKEMB + i] = p ? hspk[i] : 0.f;
        if ((i & 255) == 0) {
            int a = ba % (S_+1);
            out[OFF_MASK + ba] = (p && a > 0) ? 1.f : 0.f;
        }
    }
}

// ---------------- launch ----------------
extern "C" void kernel_launch(void* const* d_in, const int* in_sizes, int n_in,
                              void* d_out, int out_size)
{
    const int*   context  = (const int*)d_in[0];
    const int*   response = (const int*)d_in[1];
    const int*   spk      = (const int*)d_in[2];
    const float* emb_u    = (const float*)d_in[3];
    const float* emb_r    = (const float*)d_in[4];
    const float* uWih = (const float*)d_in[5];
    const float* uWhh = (const float*)d_in[6];
    const float* ubih = (const float*)d_in[7];
    const float* ubhh = (const float*)d_in[8];
    const float* cWih = (const float*)d_in[9];
    const float* cWhh = (const float*)d_in[10];
    const float* cbih = (const float*)d_in[11];
    const float* cbhh = (const float*)d_in[12];
    const float* rWih = (const float*)d_in[13];
    const float* rWhh = (const float*)d_in[14];
    const float* rbih = (const float*)d_in[15];
    const float* rbhh = (const float*)d_in[16];
    const float* sWih = (const float*)d_in[17];
    const float* sWhh = (const float*)d_in[18];
    const float* sbih = (const float*)d_in[19];
    const float* sbhh = (const float*)d_in[20];
    float* out = (float*)d_out;

    void *p;
    float *tab, *GIu, *GIc, *GIr, *hu, *hc, *hr, *hspk, *cin;
    float *WTu_i, *WTu_h, *WTc_i, *WTc_h, *WTr_i, *WTr_h, *WTs_i, *WTs_h;
    int *toku, *tokr, *pres;
    cudaGetSymbolAddress(&p, g_tables); tab  = (float*)p;
    cudaGetSymbolAddress(&p, g_GIu);    GIu  = (float*)p;
    cudaGetSymbolAddress(&p, g_GIc);    GIc  = (float*)p;
    cudaGetSymbolAddress(&p, g_GIr);    GIr  = (float*)p;
    cudaGetSymbolAddress(&p, g_hu);     hu   = (float*)p;
    cudaGetSymbolAddress(&p, g_hc);     hc   = (float*)p;
    cudaGetSymbolAddress(&p, g_hr);     hr   = (float*)p;
    cudaGetSymbolAddress(&p, g_hspk);   hspk = (float*)p;
    cudaGetSymbolAddress(&p, g_ctxin);  cin  = (float*)p;
    cudaGetSymbolAddress(&p, g_WTu_i);  WTu_i = (float*)p;
    cudaGetSymbolAddress(&p, g_WTu_h);  WTu_h = (float*)p;
    cudaGetSymbolAddress(&p, g_WTc_i);  WTc_i = (float*)p;
    cudaGetSymbolAddress(&p, g_WTc_h);  WTc_h = (float*)p;
    cudaGetSymbolAddress(&p, g_WTr_i);  WTr_i = (float*)p;
    cudaGetSymbolAddress(&p, g_WTr_h);  WTr_h = (float*)p;
    cudaGetSymbolAddress(&p, g_WTs_i);  WTs_i = (float*)p;
    cudaGetSymbolAddress(&p, g_WTs_h);  WTs_h = (float*)p;
    cudaGetSymbolAddress(&p, g_toku);   toku = (int*)p;
    cudaGetSymbolAddress(&p, g_tokr);   tokr = (int*)p;
    cudaGetSymbolAddress(&p, g_present); pres = (int*)p;

    // 1. prep
    prep_kernel<<<(PREP_TOTAL + 255)/256, 256>>>(
        context, response, spk,
        uWih, uWhh, cWih, cWhh, rWih, rWhh, sWih, sWhh,
        WTu_i, WTu_h, WTc_i, WTc_h, WTr_i, WTr_h, WTs_i, WTs_h,
        toku, tokr, hu, hc, hr, hspk, pres);

    // 2. fused GEMMs + MT19937
    mega_gemm_kernel<<<7801, 256>>>(emb_u, emb_r, toku, tokr,
                                    WTu_i, ubih, WTr_i, rbih, GIu, GIr, tab);

    // 3. utterance + response recurrences, fused per step
    for (int t = 0; t < T_; t++)
        step_ur_kernel<<<116, 256>>>(GIu, GIr, hu, hr, WTu_h, ubhh, WTr_h, rbhh,
                                     out + OFF_RESPOUT, t);

    // 4. context input + GEMM
    ctx_in_kernel<<<(MC_*2*H_ + 255)/256, 256>>>(hu, tab, spk, cin);
    gemm_ctx_kernel<<<150, 256>>>(cin, WTc_i, cbih, GIc);

    // 5. pipelined ctx + speaker chains
    for (int i = 0; i <= S_; i++)
        step_cs_kernel<<<32, 256>>>(GIc, hc, WTc_h, cbhh, out + OFF_CTXOUT,
                                    hspk, spk, WTs_i, WTs_h, sbih, sbhh, i);

    // 6. epilogue
    epilogue_kernel<<<(EPI_TOTAL + 255)/256, 256>>>(out, hr, hspk, pres);
}